// round 11
// baseline (speedup 1.0000x reference)
#include <cuda_runtime.h>
#include <cstdint>

// Problem constants (fixed by the reference: B=64, S=2048, D=256, VOCAB=32000)
#define BB 64
#define SS 2048
#define DD 256
#define SPLIT 8
#define SROWS (SS / SPLIT)     // 256 sequence rows per block
#define NBLK (BB * SPLIT)      // 512 partial blocks

// Scratch for partials: per block, 5 quantities x D floats. ~2.6 MB total.
__device__ float g_part[(size_t)NBLK * 5 * DD];
__device__ float g_wsum[NBLK];
__device__ unsigned int g_cnt[BB];   // zero-initialized; reset to 0 by finalizer

__device__ __forceinline__ float4 f4_add(float4 a, float4 b) {
    return make_float4(a.x + b.x, a.y + b.y, a.z + b.z, a.w + b.w);
}
__device__ __forceinline__ float4 f4_max(float4 a, float4 b) {
    return make_float4(fmaxf(a.x, b.x), fmaxf(a.y, b.y), fmaxf(a.z, b.z), fmaxf(a.w, b.w));
}
__device__ __forceinline__ float4 f4_min(float4 a, float4 b) {
    return make_float4(fminf(a.x, b.x), fminf(a.y, b.y), fminf(a.z, b.z), fminf(a.w, b.w));
}

// 256-bit global load (LDG.E.256): one request per 64 bytes.
__device__ __forceinline__ void ld_v8(const float* p, float4& a, float4& b) {
    uint32_t r0, r1, r2, r3, r4, r5, r6, r7;
    asm volatile("ld.global.nc.v8.b32 {%0,%1,%2,%3,%4,%5,%6,%7}, [%8];"
                 : "=r"(r0), "=r"(r1), "=r"(r2), "=r"(r3),
                   "=r"(r4), "=r"(r5), "=r"(r6), "=r"(r7)
                 : "l"(p));
    a.x = __uint_as_float(r0); a.y = __uint_as_float(r1);
    a.z = __uint_as_float(r2); a.w = __uint_as_float(r3);
    b.x = __uint_as_float(r4); b.y = __uint_as_float(r5);
    b.z = __uint_as_float(r6); b.w = __uint_as_float(r7);
}

// ---------------------------------------------------------------------------
// Fused kernel: 256 threads = 8 subgroups x 32 d-octs (8 floats per thread).
// Hot loop: 2 independent 256-bit LDG per iteration (unroll 2 -> 4 in
// flight = 256B/thread outstanding). Same bytes, half the requests vs v4.
// Last CTA per batch finalizes from L2-hot partials.
// ---------------------------------------------------------------------------
__global__ void __launch_bounds__(256)
fused_kernel(const int* __restrict__ chunk,
             const float* __restrict__ enc,     // [B, S, D] float32
             const float* __restrict__ idf,
             float* __restrict__ out)           // [B, 4*D]
{
    const int bid  = blockIdx.x;
    const int b    = bid >> 3;           // / SPLIT
    const int part = bid & (SPLIT - 1);
    const int t    = threadIdx.x;
    const int oq   = t & 31;             // d-oct index (0..31), 8 floats each
    const int sub  = t >> 5;             // subgroup (0..7)

    __shared__ float  wbuf[SROWS];       // per-row weights (1 KB)
    __shared__ float4 buf[256];          // combine buffer (4 KB)
    __shared__ float  wsh[4];
    __shared__ int    is_last;

    // Stage weights: one gather per row, done once per CTA.
    wbuf[t] = __ldg(&idf[__ldg(&chunk[b * SS + part * SROWS + t])]);
    __syncthreads();

    const float INF = __int_as_float(0x7f800000);
    // 10 float4 accumulators = lo/hi halves of the thread's 8 lanes.
    float4 awl = make_float4(0.f,0.f,0.f,0.f), awh = awl;   // sum w*x
    float4 asl = awl, ash = awl;                            // sum x
    float4 aql = awl, aqh = awl;                            // sum x*x
    float4 amxl = make_float4(-INF,-INF,-INF,-INF), amxh = amxl;
    float4 amnl = make_float4( INF, INF, INF, INF), amnh = amnl;

    const float* __restrict__ base =
        enc + ((size_t)b * SS + (size_t)(part * SROWS + sub)) * DD + oq * 8;

#define ACC4(A, V, W)                                                      \
    do {                                                                   \
        A##wl_ref.x = fmaf((W), (V).x, A##wl_ref.x);                       \
    } while (0)

#define ACCUM8(LO, HI, W)                                                  \
    do {                                                                   \
        awl.x = fmaf((W), (LO).x, awl.x); awl.y = fmaf((W), (LO).y, awl.y);\
        awl.z = fmaf((W), (LO).z, awl.z); awl.w = fmaf((W), (LO).w, awl.w);\
        awh.x = fmaf((W), (HI).x, awh.x); awh.y = fmaf((W), (HI).y, awh.y);\
        awh.z = fmaf((W), (HI).z, awh.z); awh.w = fmaf((W), (HI).w, awh.w);\
        asl = f4_add(asl, (LO)); ash = f4_add(ash, (HI));                  \
        aql.x = fmaf((LO).x,(LO).x,aql.x); aql.y = fmaf((LO).y,(LO).y,aql.y);\
        aql.z = fmaf((LO).z,(LO).z,aql.z); aql.w = fmaf((LO).w,(LO).w,aql.w);\
        aqh.x = fmaf((HI).x,(HI).x,aqh.x); aqh.y = fmaf((HI).y,(HI).y,aqh.y);\
        aqh.z = fmaf((HI).z,(HI).z,aqh.z); aqh.w = fmaf((HI).w,(HI).w,aqh.w);\
        amxl = f4_max(amxl, (LO)); amxh = f4_max(amxh, (HI));              \
        amnl = f4_min(amnl, (LO)); amnh = f4_min(amnh, (HI));              \
    } while (0)

    #pragma unroll 2
    for (int k = 0; k < SROWS; k += 16) {
        float4 a0, b0, a1, b1;
        ld_v8(base + (size_t)(k + 0) * DD, a0, b0);
        ld_v8(base + (size_t)(k + 8) * DD, a1, b1);
        const float w0 = wbuf[k + sub];
        const float w1 = wbuf[k + 8 + sub];
        ACCUM8(a0, b0, w0);
        ACCUM8(a1, b1, w1);
    }
#undef ACCUM8

    // wsum: warp 0 reduces the staged weights (deterministic tree).
    if (t < 32) {
        float ws = wbuf[t] + wbuf[t + 32] + wbuf[t + 64] + wbuf[t + 96]
                 + wbuf[t + 128] + wbuf[t + 160] + wbuf[t + 192] + wbuf[t + 224];
        #pragma unroll
        for (int off = 16; off > 0; off >>= 1)
            ws += __shfl_down_sync(0xFFFFFFFFu, ws, off);
        if (t == 0) wsh[0] = ws;
    }

    float* __restrict__ outp = g_part + (size_t)bid * 5 * DD;

    // 8-way cross-subgroup combine: 10 passes (5 quantities x lo/hi half).
    // buf[sub*32+oq] = this thread's float4; threads t<32 reduce 8 values.
#define COMBINE_SUM(V, QTY, H)                                             \
    buf[t] = (V); __syncthreads();                                         \
    if (t < 32) {                                                          \
        float4 r = f4_add(f4_add(f4_add(buf[t], buf[t+32]),                \
                                 f4_add(buf[t+64], buf[t+96])),            \
                          f4_add(f4_add(buf[t+128], buf[t+160]),           \
                                 f4_add(buf[t+192], buf[t+224])));         \
        reinterpret_cast<float4*>(outp + (QTY) * DD)[2*t + (H)] = r;       \
    }                                                                      \
    __syncthreads();
#define COMBINE_MAX(V, QTY, H)                                             \
    buf[t] = (V); __syncthreads();                                         \
    if (t < 32) {                                                          \
        float4 r = f4_max(f4_max(f4_max(buf[t], buf[t+32]),                \
                                 f4_max(buf[t+64], buf[t+96])),            \
                          f4_max(f4_max(buf[t+128], buf[t+160]),           \
                                 f4_max(buf[t+192], buf[t+224])));         \
        reinterpret_cast<float4*>(outp + (QTY) * DD)[2*t + (H)] = r;       \
    }                                                                      \
    __syncthreads();
#define COMBINE_MIN(V, QTY, H)                                             \
    buf[t] = (V); __syncthreads();                                         \
    if (t < 32) {                                                          \
        float4 r = f4_min(f4_min(f4_min(buf[t], buf[t+32]),                \
                                 f4_min(buf[t+64], buf[t+96])),            \
                          f4_min(f4_min(buf[t+128], buf[t+160]),           \
                                 f4_min(buf[t+192], buf[t+224])));         \
        reinterpret_cast<float4*>(outp + (QTY) * DD)[2*t + (H)] = r;       \
    }                                                                      \
    __syncthreads();

    COMBINE_SUM(awl, 0, 0)  COMBINE_SUM(awh, 0, 1)
    COMBINE_SUM(asl, 1, 0)  COMBINE_SUM(ash, 1, 1)
    COMBINE_SUM(aql, 2, 0)  COMBINE_SUM(aqh, 2, 1)
    COMBINE_MAX(amxl, 3, 0) COMBINE_MAX(amxh, 3, 1)
    COMBINE_MIN(amnl, 4, 0) COMBINE_MIN(amnh, 4, 1)
#undef COMBINE_SUM
#undef COMBINE_MAX
#undef COMBINE_MIN

    if (t == 0) {
        g_wsum[bid] = wsh[0];
        __threadfence();   // release this CTA's partials
    }
    __syncthreads();

    // Last CTA of this batch finalizes.
    if (t == 0) {
        unsigned int old = atomicAdd(&g_cnt[b], 1u);
        is_last = (old == SPLIT - 1);
    }
    __syncthreads();
    if (!is_last) return;
    if (t == 0) {
        __threadfence();           // acquire side
        g_cnt[b] = 0;              // reset for next graph replay
    }
    __syncthreads();

    // ---- Finalize batch b: combine SPLIT=8 partials (L2-hot, ~40 KB) ----
    const int q4   = t & 63;       // d-quad index for finalize
    const int sub4 = t >> 6;       // 4 subgroups

    float4 mw = make_float4(0.f, 0.f, 0.f, 0.f);
    float4 sm = make_float4(0.f, 0.f, 0.f, 0.f);
    float4 sq = make_float4(0.f, 0.f, 0.f, 0.f);
    float4 mx = make_float4(-INF, -INF, -INF, -INF);
    float4 mn = make_float4( INF,  INF,  INF,  INF);
    float ws = 0.f;

    #pragma unroll
    for (int j = 0; j < 2; ++j) {
        const int p = sub4 * 2 + j;
        const int pbid = b * SPLIT + p;
        const float4* __restrict__ pp =
            reinterpret_cast<const float4*>(g_part + (size_t)pbid * 5 * DD);
        mw = f4_add(mw, __ldcg(&pp[0 * 64 + q4]));
        sm = f4_add(sm, __ldcg(&pp[1 * 64 + q4]));
        sq = f4_add(sq, __ldcg(&pp[2 * 64 + q4]));
        mx = f4_max(mx, __ldcg(&pp[3 * 64 + q4]));
        mn = f4_min(mn, __ldcg(&pp[4 * 64 + q4]));
        ws += __ldcg(&g_wsum[pbid]);
    }

    if (q4 == 0) wsh[sub4] = ws;

    float4 rw, rs, rq, rx, rn;
    buf[t] = mw; __syncthreads();
    if (sub4 == 0) rw = f4_add(f4_add(buf[q4], buf[q4 + 64]), f4_add(buf[q4 + 128], buf[q4 + 192]));
    __syncthreads();
    buf[t] = sm; __syncthreads();
    if (sub4 == 0) rs = f4_add(f4_add(buf[q4], buf[q4 + 64]), f4_add(buf[q4 + 128], buf[q4 + 192]));
    __syncthreads();
    buf[t] = sq; __syncthreads();
    if (sub4 == 0) rq = f4_add(f4_add(buf[q4], buf[q4 + 64]), f4_add(buf[q4 + 128], buf[q4 + 192]));
    __syncthreads();
    buf[t] = mx; __syncthreads();
    if (sub4 == 0) rx = f4_max(f4_max(buf[q4], buf[q4 + 64]), f4_max(buf[q4 + 128], buf[q4 + 192]));
    __syncthreads();
    buf[t] = mn; __syncthreads();
    if (sub4 == 0) {
        rn = f4_min(f4_min(buf[q4], buf[q4 + 64]), f4_min(buf[q4 + 128], buf[q4 + 192]));

        const float wsum = wsh[0] + wsh[1] + wsh[2] + wsh[3];
        const float inv_w = 1.0f / wsum;
        const float inv_s = 1.0f / (float)SS;
        const float inv_n1 = 1.0f / (float)(SS - 1);

        float4 mean = make_float4(rw.x * inv_w, rw.y * inv_w, rw.z * inv_w, rw.w * inv_w);
        float4 var;
        var.x = fmaxf((rq.x - rs.x * rs.x * inv_s) * inv_n1, 0.f);
        var.y = fmaxf((rq.y - rs.y * rs.y * inv_s) * inv_n1, 0.f);
        var.z = fmaxf((rq.z - rs.z * rs.z * inv_s) * inv_n1, 0.f);
        var.w = fmaxf((rq.w - rs.w * rs.w * inv_s) * inv_n1, 0.f);
        float4 sd = make_float4(sqrtf(var.x), sqrtf(var.y), sqrtf(var.z), sqrtf(var.w));

        float4* __restrict__ o = reinterpret_cast<float4*>(out + (size_t)b * 4 * DD);
        o[0 * 64 + q4] = mean;
        o[1 * 64 + q4] = rx;
        o[2 * 64 + q4] = rn;
        o[3 * 64 + q4] = sd;
    }
}

extern "C" void kernel_launch(void* const* d_in, const int* in_sizes, int n_in,
                              void* d_out, int out_size)
{
    const int*   chunk = (const int*)d_in[0];     // [B, S] int32
    const float* enc   = (const float*)d_in[1];   // [B, S, D] float32
    const float* idf   = (const float*)d_in[2];   // [VOCAB] float32
    float* out = (float*)d_out;                   // [B, 4*D] float32

    fused_kernel<<<NBLK, 256>>>(chunk, enc, idf, out);
}

// round 12
// speedup vs baseline: 1.3509x; 1.3509x over previous
#include <cuda_runtime.h>
#include <cstdint>

// Problem constants (fixed by the reference: B=64, S=2048, D=256, VOCAB=32000)
#define BB 64
#define SS 2048
#define DD 256
#define SPLIT 8
#define SROWS (SS / SPLIT)     // 256 sequence rows per block
#define NBLK (BB * SPLIT)      // 512 partial blocks

#define STAGES 4
#define TROWS 8                          // rows per stage
#define STAGE_BYTES (TROWS * DD * 4)     // 8192 bytes
#define NTILES (SROWS / TROWS)           // 32 tiles per CTA

// Scratch for partials: per block, 5 quantities x D floats. ~2.6 MB total.
__device__ float g_part[(size_t)NBLK * 5 * DD];
__device__ float g_wsum[NBLK];
__device__ unsigned int g_cnt[BB];   // zero-initialized; reset to 0 by finalizer

__device__ __forceinline__ float4 f4_add(float4 a, float4 b) {
    return make_float4(a.x + b.x, a.y + b.y, a.z + b.z, a.w + b.w);
}
__device__ __forceinline__ float4 f4_max(float4 a, float4 b) {
    return make_float4(fmaxf(a.x, b.x), fmaxf(a.y, b.y), fmaxf(a.z, b.z), fmaxf(a.w, b.w));
}
__device__ __forceinline__ float4 f4_min(float4 a, float4 b) {
    return make_float4(fminf(a.x, b.x), fminf(a.y, b.y), fminf(a.z, b.z), fminf(a.w, b.w));
}

__device__ __forceinline__ uint32_t smem_u32(const void* p) {
    return (uint32_t)__cvta_generic_to_shared(p);
}

#define MBAR_INIT(addr, cnt)                                                  \
    asm volatile("mbarrier.init.shared.b64 [%0], %1;"                         \
                 :: "r"(addr), "r"(cnt) : "memory")

#define MBAR_EXPECT_TX(addr, bytes)                                           \
    asm volatile("mbarrier.arrive.expect_tx.shared.b64 _, [%0], %1;"          \
                 :: "r"(addr), "r"(bytes) : "memory")

#define MBAR_ARRIVE(addr)                                                     \
    asm volatile("mbarrier.arrive.shared.b64 _, [%0];"                        \
                 :: "r"(addr) : "memory")

#define MBAR_WAIT(addr, parity)                                               \
    asm volatile(                                                             \
        "{\n\t"                                                               \
        ".reg .pred P1;\n\t"                                                  \
        "WAIT_LOOP_%=:\n\t"                                                   \
        "mbarrier.try_wait.parity.acquire.cta.shared::cta.b64 P1, [%0], %1, 0x989680;\n\t" \
        "@P1 bra.uni WAIT_DONE_%=;\n\t"                                       \
        "bra.uni WAIT_LOOP_%=;\n\t"                                           \
        "WAIT_DONE_%=:\n\t"                                                   \
        "}"                                                                   \
        :: "r"(addr), "r"(parity) : "memory")

#define BULK_G2S(dst, src, bytes, mbar)                                       \
    asm volatile(                                                             \
        "cp.async.bulk.shared::cta.global.mbarrier::complete_tx::bytes "      \
        "[%0], [%1], %2, [%3];"                                               \
        :: "r"(dst), "l"(src), "r"(bytes), "r"(mbar) : "memory")

// ---------------------------------------------------------------------------
// Fused kernel, TMA-bulk pipeline version (best measured configuration).
// 128 threads = 2 subgroups x 64 d-quads. Per CTA: 256 contiguous rows
// (256 KB) streamed as 32 x 8KB cp.async.bulk tiles through a 4-stage
// smem ring; consumers accumulate from smem (conflict-free LDS.128).
// Last CTA per batch finalizes from L2-hot partials.
// ---------------------------------------------------------------------------
__global__ void __launch_bounds__(128)
fused_kernel(const int* __restrict__ chunk,
             const float* __restrict__ enc,     // [B, S, D] float32
             const float* __restrict__ idf,
             float* __restrict__ out)           // [B, 4*D]
{
    const int bid  = blockIdx.x;
    const int b    = bid >> 3;           // / SPLIT
    const int part = bid & (SPLIT - 1);
    const int t    = threadIdx.x;
    const int q    = t & 63;             // d-quad index (0..63)
    const int sub  = t >> 6;             // subgroup (0..1)

    __shared__ __align__(128) float4 stage[STAGES][TROWS * 64];  // 32 KB
    __shared__ float  wbuf[SROWS];       // per-row weights (1 KB)
    __shared__ float4 buf[128];          // combine buffer (2 KB)
    __shared__ float  wsh[2];
    __shared__ int    is_last;
    __shared__ __align__(8) unsigned long long mbar_full[STAGES];
    __shared__ __align__(8) unsigned long long mbar_empty[STAGES];

    // Stage weights: 256 rows, 128 threads -> 2 gathers per thread.
    {
        const int s = b * SS + part * SROWS;
        wbuf[t]       = __ldg(&idf[__ldg(&chunk[s + t])]);
        wbuf[t + 128] = __ldg(&idf[__ldg(&chunk[s + t + 128])]);
    }

    if (t == 0) {
        #pragma unroll
        for (int j = 0; j < STAGES; ++j) {
            MBAR_INIT(smem_u32(&mbar_full[j]), 1);
            MBAR_INIT(smem_u32(&mbar_empty[j]), 128);
        }
    }
    __syncthreads();

    const char* __restrict__ src =
        (const char*)enc + ((size_t)b * SS + (size_t)part * SROWS) * DD * 4;

    // Prologue: fill all STAGES slots.
    if (t == 0) {
        #pragma unroll
        for (int j = 0; j < STAGES; ++j) {
            const uint32_t fb = smem_u32(&mbar_full[j]);
            MBAR_EXPECT_TX(fb, STAGE_BYTES);
            BULK_G2S(smem_u32(&stage[j][0]), src + (size_t)j * STAGE_BYTES,
                     STAGE_BYTES, fb);
        }
    }

    const float INF = __int_as_float(0x7f800000);
    float4 aw = make_float4(0.f, 0.f, 0.f, 0.f);   // sum w*x
    float4 as = make_float4(0.f, 0.f, 0.f, 0.f);   // sum x
    float4 aq = make_float4(0.f, 0.f, 0.f, 0.f);   // sum x*x
    float4 amx = make_float4(-INF, -INF, -INF, -INF);
    float4 amn = make_float4( INF,  INF,  INF,  INF);

#define ACCUM(V, W)                                                        \
    do {                                                                   \
        aw.x = fmaf((W), (V).x, aw.x); aw.y = fmaf((W), (V).y, aw.y);      \
        aw.z = fmaf((W), (V).z, aw.z); aw.w = fmaf((W), (V).w, aw.w);      \
        as = f4_add(as, (V));                                              \
        aq.x = fmaf((V).x, (V).x, aq.x); aq.y = fmaf((V).y, (V).y, aq.y);  \
        aq.z = fmaf((V).z, (V).z, aq.z); aq.w = fmaf((V).w, (V).w, aq.w);  \
        amx = f4_max(amx, (V));                                            \
        amn = f4_min(amn, (V));                                            \
    } while (0)

    for (int i = 0; i < NTILES; ++i) {
        const int slot = i & (STAGES - 1);
        const int r    = i / STAGES;          // reuse count of this slot

        MBAR_WAIT(smem_u32(&mbar_full[slot]), r & 1);

        // Consume 8 rows: this thread handles rows sub, sub+2, sub+4, sub+6.
        const float4* __restrict__ sp = &stage[slot][0];
        const float4 v0 = sp[(sub + 0) * 64 + q];
        const float4 v1 = sp[(sub + 2) * 64 + q];
        const float4 v2 = sp[(sub + 4) * 64 + q];
        const float4 v3 = sp[(sub + 6) * 64 + q];
        const float w0 = wbuf[i * TROWS + sub + 0];
        const float w1 = wbuf[i * TROWS + sub + 2];
        const float w2 = wbuf[i * TROWS + sub + 4];
        const float w3 = wbuf[i * TROWS + sub + 6];
        ACCUM(v0, w0); ACCUM(v1, w1); ACCUM(v2, w2); ACCUM(v3, w3);

        MBAR_ARRIVE(smem_u32(&mbar_empty[slot]));

        // Producer: refill this slot with tile i+STAGES.
        if (t == 0 && i + STAGES < NTILES) {
            MBAR_WAIT(smem_u32(&mbar_empty[slot]), r & 1);
            const uint32_t fb = smem_u32(&mbar_full[slot]);
            MBAR_EXPECT_TX(fb, STAGE_BYTES);
            BULK_G2S(smem_u32(&stage[slot][0]),
                     src + (size_t)(i + STAGES) * STAGE_BYTES, STAGE_BYTES, fb);
        }
    }
#undef ACCUM

    // wsum: warp 0 reduces the staged weights (deterministic tree).
    if (t < 32) {
        float ws = wbuf[t] + wbuf[t + 32] + wbuf[t + 64] + wbuf[t + 96]
                 + wbuf[t + 128] + wbuf[t + 160] + wbuf[t + 192] + wbuf[t + 224];
        #pragma unroll
        for (int off = 16; off > 0; off >>= 1)
            ws += __shfl_down_sync(0xFFFFFFFFu, ws, off);
        if (t == 0) wsh[0] = ws;
    }

    float* __restrict__ outp = g_part + (size_t)bid * 5 * DD;

    // Cross-subgroup combine through shared memory, one quantity at a time.
    buf[t] = aw; __syncthreads();
    if (sub == 0)
        reinterpret_cast<float4*>(outp + 0 * DD)[q] = f4_add(buf[q], buf[q + 64]);
    __syncthreads();
    buf[t] = as; __syncthreads();
    if (sub == 0)
        reinterpret_cast<float4*>(outp + 1 * DD)[q] = f4_add(buf[q], buf[q + 64]);
    __syncthreads();
    buf[t] = aq; __syncthreads();
    if (sub == 0)
        reinterpret_cast<float4*>(outp + 2 * DD)[q] = f4_add(buf[q], buf[q + 64]);
    __syncthreads();
    buf[t] = amx; __syncthreads();
    if (sub == 0)
        reinterpret_cast<float4*>(outp + 3 * DD)[q] = f4_max(buf[q], buf[q + 64]);
    __syncthreads();
    buf[t] = amn; __syncthreads();
    if (sub == 0) {
        reinterpret_cast<float4*>(outp + 4 * DD)[q] = f4_min(buf[q], buf[q + 64]);
        if (q == 0) g_wsum[bid] = wsh[0];
        __threadfence();   // release this CTA's partials (writers fence)
    }
    __syncthreads();

    // Last CTA of this batch finalizes.
    if (t == 0) {
        unsigned int old = atomicAdd(&g_cnt[b], 1u);
        is_last = (old == SPLIT - 1);
    }
    __syncthreads();
    if (!is_last) return;
    if (t == 0) {
        __threadfence();           // acquire side
        g_cnt[b] = 0;              // reset for next graph replay
    }
    __syncthreads();

    // ---- Finalize batch b: combine SPLIT=8 partials (L2-hot, ~40 KB) ----
    float4 mw = make_float4(0.f, 0.f, 0.f, 0.f);
    float4 sm = make_float4(0.f, 0.f, 0.f, 0.f);
    float4 sq = make_float4(0.f, 0.f, 0.f, 0.f);
    float4 mx = make_float4(-INF, -INF, -INF, -INF);
    float4 mn = make_float4( INF,  INF,  INF,  INF);
    float ws = 0.f;

    #pragma unroll
    for (int j = 0; j < 4; ++j) {
        const int p = sub * 4 + j;
        const int pbid = b * SPLIT + p;
        const float4* __restrict__ pp =
            reinterpret_cast<const float4*>(g_part + (size_t)pbid * 5 * DD);
        mw = f4_add(mw, __ldcg(&pp[0 * 64 + q]));
        sm = f4_add(sm, __ldcg(&pp[1 * 64 + q]));
        sq = f4_add(sq, __ldcg(&pp[2 * 64 + q]));
        mx = f4_max(mx, __ldcg(&pp[3 * 64 + q]));
        mn = f4_min(mn, __ldcg(&pp[4 * 64 + q]));
        ws += __ldcg(&g_wsum[pbid]);
    }

    if (q == 0) wsh[sub] = ws;

    float4 rw, rs, rq, rx, rn;
    buf[t] = mw; __syncthreads();
    if (sub == 0) rw = f4_add(buf[q], buf[q + 64]);
    __syncthreads();
    buf[t] = sm; __syncthreads();
    if (sub == 0) rs = f4_add(buf[q], buf[q + 64]);
    __syncthreads();
    buf[t] = sq; __syncthreads();
    if (sub == 0) rq = f4_add(buf[q], buf[q + 64]);
    __syncthreads();
    buf[t] = mx; __syncthreads();
    if (sub == 0) rx = f4_max(buf[q], buf[q + 64]);
    __syncthreads();
    buf[t] = mn; __syncthreads();
    if (sub == 0) {
        rn = f4_min(buf[q], buf[q + 64]);

        const float wsum = wsh[0] + wsh[1];
        const float inv_w = 1.0f / wsum;
        const float inv_s = 1.0f / (float)SS;
        const float inv_n1 = 1.0f / (float)(SS - 1);

        float4 mean = make_float4(rw.x * inv_w, rw.y * inv_w, rw.z * inv_w, rw.w * inv_w);
        float4 var;
        var.x = fmaxf((rq.x - rs.x * rs.x * inv_s) * inv_n1, 0.f);
        var.y = fmaxf((rq.y - rs.y * rs.y * inv_s) * inv_n1, 0.f);
        var.z = fmaxf((rq.z - rs.z * rs.z * inv_s) * inv_n1, 0.f);
        var.w = fmaxf((rq.w - rs.w * rs.w * inv_s) * inv_n1, 0.f);
        float4 sd = make_float4(sqrtf(var.x), sqrtf(var.y), sqrtf(var.z), sqrtf(var.w));

        float4* __restrict__ o = reinterpret_cast<float4*>(out + (size_t)b * 4 * DD);
        o[0 * 64 + q] = mean;
        o[1 * 64 + q] = rx;
        o[2 * 64 + q] = rn;
        o[3 * 64 + q] = sd;
    }
}

extern "C" void kernel_launch(void* const* d_in, const int* in_sizes, int n_in,
                              void* d_out, int out_size)
{
    const int*   chunk = (const int*)d_in[0];     // [B, S] int32
    const float* enc   = (const float*)d_in[1];   // [B, S, D] float32
    const float* idf   = (const float*)d_in[2];   // [VOCAB] float32
    float* out = (float*)d_out;                   // [B, 4*D] float32

    fused_kernel<<<NBLK, 128>>>(chunk, enc, idf, out);
}